// round 8
// baseline (speedup 1.0000x reference)
#include <cuda_runtime.h>
#include <cuda_bf16.h>
#include <math.h>
#include <stdint.h>

// Problem constants
#define B_   64
#define P_   196
#define ENC_ 2048
#define H_   512
#define E_   512
#define A_   512
#define V_   30000
#define T_   20
#define GH_  2048   // 4*H
#define KCAT 3072   // E + ENC + H
#define MPRED (19 * B_)
#define KSPLIT_GATES 8
#define KSPLIT_GATE  4

// ---------------- scratch (static device memory; allocation-free) ----------------
__device__ __align__(16) float g_att_enc[B_ * P_ * A_];
__device__ __align__(16) float g_alpha [B_ * P_];
__device__ __align__(16) float g_sh   [B_ * H_];
__device__ __align__(16) float g_h    [B_ * H_];
__device__ __align__(16) float g_c    [B_ * H_];
__device__ __align__(16) float g_mean [B_ * ENC_];
__device__ __align__(16) float g_bcat [GH_];
__device__ __align__(16) float g_hall [MPRED * H_];
__device__ __align__(16) float g_gate_part [KSPLIT_GATE  * B_ * ENC_]; // gate split-K partials
__device__ __align__(16) float g_gates_part[KSPLIT_GATES * B_ * GH_];  // gates split-K partials
__device__ int g_tok64;

// bf16 split operands (hi + lo error-compensated)
__device__ __align__(16) __nv_bfloat16 g_enc_hi [B_ * P_ * ENC_];
__device__ __align__(16) __nv_bfloat16 g_enc_lo [B_ * P_ * ENC_];
__device__ __align__(16) __nv_bfloat16 g_We_hi  [A_ * ENC_];
__device__ __align__(16) __nv_bfloat16 g_We_lo  [A_ * ENC_];
__device__ __align__(16) __nv_bfloat16 g_Wfc_hi [V_ * H_];
__device__ __align__(16) __nv_bfloat16 g_Wfc_lo [V_ * H_];
__device__ __align__(16) __nv_bfloat16 g_Wcat_hi[GH_ * KCAT];
__device__ __align__(16) __nv_bfloat16 g_Wcat_lo[GH_ * KCAT];
__device__ __align__(16) __nv_bfloat16 g_inp_hi [B_ * KCAT];
__device__ __align__(16) __nv_bfloat16 g_inp_lo [B_ * KCAT];
__device__ __align__(16) __nv_bfloat16 g_hall_hi[MPRED * H_];
__device__ __align__(16) __nv_bfloat16 g_hall_lo[MPRED * H_];

__device__ __forceinline__ float sigf(float x) { return 1.f / (1.f + __expf(-x)); }

// ================= bf16 tensor-core GEMM: C[M,N] = A[M,K] * B[N,K]^T ==========
// hi/lo error-compensated (hi*hi + hi*lo + lo*hi), fp32 accum.
// mode 0: C[m*ldc+n] = acc + bias[n]
// mode 2: pred scatter: row m=(t*64+b) -> C[b*T*V + t*V + n] = acc + bias[n]
//         (grid: x = M-tiles, y = N-tiles)
// mode 3: partial: C[(z*M + m)*ldc + n] = acc   (split-K via z, no bias)
#define LDSM_ 40

__device__ __forceinline__ void ldsm4(uint32_t* r, uint32_t addr)
{
    asm volatile("ldmatrix.sync.aligned.m8n8.x4.shared.b16 {%0,%1,%2,%3}, [%4];"
                 : "=r"(r[0]), "=r"(r[1]), "=r"(r[2]), "=r"(r[3]) : "r"(addr));
}

__device__ __forceinline__ void mma16816(float* c, const uint32_t* a, uint32_t b0, uint32_t b1)
{
    asm volatile("mma.sync.aligned.m16n8k16.row.col.f32.bf16.bf16.f32 "
                 "{%0,%1,%2,%3}, {%4,%5,%6,%7}, {%8,%9}, {%0,%1,%2,%3};"
                 : "+f"(c[0]), "+f"(c[1]), "+f"(c[2]), "+f"(c[3])
                 : "r"(a[0]), "r"(a[1]), "r"(a[2]), "r"(a[3]), "r"(b0), "r"(b1));
}

__global__ __launch_bounds__(256)
void mma_gemm_kernel(const __nv_bfloat16* __restrict__ Ahi, const __nv_bfloat16* __restrict__ Alo,
                     const __nv_bfloat16* __restrict__ Bhi, const __nv_bfloat16* __restrict__ Blo,
                     float* __restrict__ C, const float* __restrict__ bias,
                     int M, int N, int K, int ldc, int kchunk, int mode)
{
    __shared__ __nv_bfloat16 sAh[64 * LDSM_], sAl[64 * LDSM_];
    __shared__ __nv_bfloat16 sBh[64 * LDSM_], sBl[64 * LDSM_];

    const int tid  = threadIdx.x;
    const int lane = tid & 31;
    const int warp = tid >> 5;
    const int wm = (warp & 1) * 32;
    const int wn = (warp >> 1) * 16;

    int m0, n0;
    if (mode == 2) { m0 = blockIdx.x * 64; n0 = blockIdx.y * 64; }
    else           { n0 = blockIdx.x * 64; m0 = blockIdx.y * 64; }

    const int kbeg = blockIdx.z * kchunk;
    const int kend = kbeg + kchunk;

    float acc[2][2][4];
#pragma unroll
    for (int i = 0; i < 2; ++i)
#pragma unroll
        for (int j = 0; j < 2; ++j)
#pragma unroll
            for (int q = 0; q < 4; ++q) acc[i][j][q] = 0.f;

    // loaders: all 256 threads cover a full 64x32 tile per array
    const int lrow   = tid >> 2;
    const int lchunk = (tid & 3) << 3;

    const uint32_t sAh_b = (uint32_t)__cvta_generic_to_shared(sAh);
    const uint32_t sAl_b = (uint32_t)__cvta_generic_to_shared(sAl);
    const uint32_t sBh_b = (uint32_t)__cvta_generic_to_shared(sBh);
    const uint32_t sBl_b = (uint32_t)__cvta_generic_to_shared(sBl);

    const int fr   = lane & 15;
    const int fcof = (lane >> 4) << 3;
    const int aoff0 = (wm +  0 + fr) * LDSM_ + fcof;
    const int aoff1 = (wm + 16 + fr) * LDSM_ + fcof;
    const int boff  = (wn +       fr) * LDSM_ + fcof;

    for (int k0 = kbeg; k0 < kend; k0 += 32) {
        {
            size_t gofs = (size_t)(m0 + lrow) * K + k0 + lchunk;
            *(uint4*)&sAh[lrow * LDSM_ + lchunk] = *(const uint4*)(Ahi + gofs);
            *(uint4*)&sAl[lrow * LDSM_ + lchunk] = *(const uint4*)(Alo + gofs);
        }
        {
            uint4 vh = make_uint4(0u, 0u, 0u, 0u), vl = vh;
            int n = n0 + lrow;
            if (n < N) {
                size_t gofs = (size_t)n * K + k0 + lchunk;
                vh = *(const uint4*)(Bhi + gofs);
                vl = *(const uint4*)(Blo + gofs);
            }
            *(uint4*)&sBh[lrow * LDSM_ + lchunk] = vh;
            *(uint4*)&sBl[lrow * LDSM_ + lchunk] = vl;
        }
        __syncthreads();

#pragma unroll
        for (int kk = 0; kk < 32; kk += 16) {
            uint32_t ah0[4], ah1[4], al0[4], al1[4], bh[4], bl[4];
            ldsm4(ah0, sAh_b + (uint32_t)(aoff0 + kk) * 2);
            ldsm4(ah1, sAh_b + (uint32_t)(aoff1 + kk) * 2);
            ldsm4(al0, sAl_b + (uint32_t)(aoff0 + kk) * 2);
            ldsm4(al1, sAl_b + (uint32_t)(aoff1 + kk) * 2);
            ldsm4(bh,  sBh_b + (uint32_t)(boff  + kk) * 2);
            ldsm4(bl,  sBl_b + (uint32_t)(boff  + kk) * 2);
            mma16816(acc[0][0], ah0, bh[0], bh[2]);
            mma16816(acc[0][1], ah0, bh[1], bh[3]);
            mma16816(acc[1][0], ah1, bh[0], bh[2]);
            mma16816(acc[1][1], ah1, bh[1], bh[3]);
            mma16816(acc[0][0], ah0, bl[0], bl[2]);
            mma16816(acc[0][1], ah0, bl[1], bl[3]);
            mma16816(acc[1][0], ah1, bl[0], bl[2]);
            mma16816(acc[1][1], ah1, bl[1], bl[3]);
            mma16816(acc[0][0], al0, bh[0], bh[2]);
            mma16816(acc[0][1], al0, bh[1], bh[3]);
            mma16816(acc[1][0], al1, bh[0], bh[2]);
            mma16816(acc[1][1], al1, bh[1], bh[3]);
        }
        __syncthreads();
    }

#pragma unroll
    for (int mt = 0; mt < 2; ++mt) {
#pragma unroll
        for (int nt = 0; nt < 2; ++nt) {
            int row = m0 + wm + mt * 16 + (lane >> 2);
            int col = n0 + wn + nt * 8 + ((lane & 3) << 1);
            const float* a = acc[mt][nt];
#pragma unroll
            for (int hh = 0; hh < 2; ++hh) {
                int rr = row + hh * 8;
                float v0 = a[hh * 2 + 0], v1 = a[hh * 2 + 1];
                if (mode == 0) {
                    if (col < N)     C[(size_t)rr * ldc + col]     = v0 + (bias ? bias[col]     : 0.f);
                    if (col + 1 < N) C[(size_t)rr * ldc + col + 1] = v1 + (bias ? bias[col + 1] : 0.f);
                } else if (mode == 3) {
                    size_t o = ((size_t)blockIdx.z * M + rr) * ldc;
                    if (col < N)     C[o + col]     = v0;
                    if (col + 1 < N) C[o + col + 1] = v1;
                } else {
                    int tt = rr >> 6, bb = rr & 63;
                    size_t o = (size_t)bb * T_ * V_ + (size_t)tt * V_;
                    if (col < N)     C[o + col]     = v0 + bias[col];
                    if (col + 1 < N) C[o + col + 1] = v1 + bias[col + 1];
                }
            }
        }
    }
}

// ---------------- fp32 SIMT SGEMM: C = A[M,K]*B[N,K]^T ----------------
// mode 1: atomicAdd (split-K, C pre-initialized)
// mode 2: partial: C[(z*M+m)*ldc + n] = acc
#define BM 64
#define BN 64
#define BK 16

__global__ __launch_bounds__(256)
void sgemm_kernel(const float* __restrict__ Amat, const float* __restrict__ Bmat,
                  float* __restrict__ C, const float* __restrict__ bias,
                  int M, int N, int K, int ldc, int kchunk, int mode)
{
    __shared__ float As[BK][BM + 4];
    __shared__ float Bs[BK][BN + 4];

    const int tid = threadIdx.x;
    const int tx = tid & 15;
    const int ty = tid >> 4;
    const int m0 = blockIdx.y * BM;
    const int n0 = blockIdx.x * BN;
    const int kbeg = blockIdx.z * kchunk;
    const int kend = kbeg + kchunk;
    const int lr = tid >> 2;
    const int lc = (tid & 3) << 2;

    float acc[4][4] = {};

    for (int k0 = kbeg; k0 < kend; k0 += BK) {
        float4 a4 = make_float4(0.f, 0.f, 0.f, 0.f);
        int am = m0 + lr;
        if (am < M) a4 = *(const float4*)(Amat + (size_t)am * K + k0 + lc);
        As[lc + 0][lr] = a4.x; As[lc + 1][lr] = a4.y;
        As[lc + 2][lr] = a4.z; As[lc + 3][lr] = a4.w;

        float4 b4 = make_float4(0.f, 0.f, 0.f, 0.f);
        int bn = n0 + lr;
        if (bn < N) b4 = *(const float4*)(Bmat + (size_t)bn * K + k0 + lc);
        Bs[lc + 0][lr] = b4.x; Bs[lc + 1][lr] = b4.y;
        Bs[lc + 2][lr] = b4.z; Bs[lc + 3][lr] = b4.w;

        __syncthreads();
#pragma unroll
        for (int k = 0; k < BK; ++k) {
            float4 ra = *(const float4*)&As[k][ty << 2];
            float4 rb = *(const float4*)&Bs[k][tx << 2];
            acc[0][0] += ra.x * rb.x; acc[0][1] += ra.x * rb.y;
            acc[0][2] += ra.x * rb.z; acc[0][3] += ra.x * rb.w;
            acc[1][0] += ra.y * rb.x; acc[1][1] += ra.y * rb.y;
            acc[1][2] += ra.y * rb.z; acc[1][3] += ra.y * rb.w;
            acc[2][0] += ra.z * rb.x; acc[2][1] += ra.z * rb.y;
            acc[2][2] += ra.z * rb.z; acc[2][3] += ra.z * rb.w;
            acc[3][0] += ra.w * rb.x; acc[3][1] += ra.w * rb.y;
            acc[3][2] += ra.w * rb.z; acc[3][3] += ra.w * rb.w;
        }
        __syncthreads();
    }

#pragma unroll
    for (int i = 0; i < 4; ++i) {
        int m = m0 + (ty << 2) + i;
        if (m >= M) continue;
#pragma unroll
        for (int j = 0; j < 4; ++j) {
            int n = n0 + (tx << 2) + j;
            if (n >= N) continue;
            if (mode == 1)      atomicAdd(&C[(size_t)m * ldc + n], acc[i][j]);
            else if (mode == 2) C[((size_t)blockIdx.z * M + m) * ldc + n] = acc[i][j];
            else                C[(size_t)m * ldc + n] = acc[i][j] + (bias ? bias[n] : 0.f);
        }
    }
}

// ================= Kernel S: att_h + scores + softmax (one block per b) =======
__global__ __launch_bounds__(256)
void attn_scores_kernel(const float* __restrict__ Wh, const float* __restrict__ bh,
                        const float* __restrict__ Wa, const float* __restrict__ ba)
{
    __shared__ float s_h [H_];
    __shared__ float s_ah[A_];
    __shared__ float s_wa[A_];
    __shared__ float s_sc[256];   // scores, padded

    const int b = blockIdx.x;
    const int tid = threadIdx.x;
    const int lane = tid & 31;
    const int warp = tid >> 5;

    for (int i = tid; i < H_; i += 256) {
        s_h[i]  = g_h[b * H_ + i];
        s_wa[i] = Wa[i];
    }
    __syncthreads();

    // att_h[j] = bh[j] + sum_k h[k] * Wh[j,k]   (warp-per-j dot, coalesced)
    for (int j = warp * 64; j < warp * 64 + 64; ++j) {
        const float* wr = Wh + (size_t)j * H_;
        float s = 0.f;
#pragma unroll
        for (int k = lane; k < H_; k += 32) s += s_h[k] * wr[k];
#pragma unroll
        for (int o = 16; o; o >>= 1) s += __shfl_xor_sync(0xffffffff, s, o);
        if (lane == 0) s_ah[j] = s + bh[j];
    }
    __syncthreads();

    // scores[p] = sum_a relu(att_enc + att_h) * Wa + ba
    for (int p = warp; p < P_; p += 8) {
        const float* row = g_att_enc + ((size_t)(b * P_ + p)) * A_;
        float s = 0.f;
#pragma unroll
        for (int a = lane; a < A_; a += 32) {
            float v = row[a] + s_ah[a];
            s += fmaxf(v, 0.f) * s_wa[a];
        }
#pragma unroll
        for (int o = 16; o; o >>= 1) s += __shfl_xor_sync(0xffffffff, s, o);
        if (lane == 0) s_sc[p] = s + ba[0];
    }
    if (tid >= P_ && tid < 256) s_sc[tid] = -1e30f;
    __syncthreads();

    // softmax over 196
    __shared__ float red[256];
    float v = s_sc[tid];
    red[tid] = v; __syncthreads();
    for (int s = 128; s; s >>= 1) { if (tid < s) red[tid] = fmaxf(red[tid], red[tid + s]); __syncthreads(); }
    float mx = red[0]; __syncthreads();
    float e = (tid < P_) ? __expf(v - mx) : 0.f;
    red[tid] = e; __syncthreads();
    for (int s = 128; s; s >>= 1) { if (tid < s) red[tid] += red[tid + s]; __syncthreads(); }
    float inv = 1.f / red[0];
    if (tid < P_) g_alpha[b * P_ + tid] = e * inv;
}

// ========= Kernel W: weighted + gate-reduce + inp build + bf16 split ==========
// grid: x = KCAT/256 chunks, y = b
__global__ __launch_bounds__(256)
void build_inp_fused_kernel(const float* __restrict__ enc, const void* __restrict__ cap,
                            const float* __restrict__ emb, const float* __restrict__ bg, int t)
{
    __shared__ float sa[P_];
    const int b = blockIdx.y;
    const int j = blockIdx.x * 256 + threadIdx.x;

    float v;
    if (j < E_) {
        long long tok = g_tok64 ? ((const long long*)cap)[b * T_ + t]
                                : (long long)((const int*)cap)[b * T_ + t];
        v = emb[(size_t)tok * E_ + j];
    } else if (j < E_ + ENC_) {
        for (int i = threadIdx.x; i < P_; i += 256) sa[i] = g_alpha[b * P_ + i];
        __syncthreads();
        const int e = j - E_;
        // weighted
        const float* base = enc + (size_t)b * P_ * ENC_ + e;
        float w = 0.f;
#pragma unroll 4
        for (int p = 0; p < P_; ++p) w += sa[p] * base[(size_t)p * ENC_];
        // gate = bg + sum of split-K partials
        float gt = bg[e];
#pragma unroll
        for (int z = 0; z < KSPLIT_GATE; ++z)
            gt += g_gate_part[((size_t)z * B_ + b) * ENC_ + e];
        v = w * gt;
    } else {
        v = g_h[b * H_ + (j - E_ - ENC_)];
    }
    __nv_bfloat16 h = __float2bfloat16_rn(v);
    g_inp_hi[b * KCAT + j] = h;
    g_inp_lo[b * KCAT + j] = __float2bfloat16_rn(v - __bfloat162float(h));
}

// ---------------- small kernels ----------------

__global__ __launch_bounds__(256)
void split_kernel(const float* __restrict__ src, __nv_bfloat16* __restrict__ hi,
                  __nv_bfloat16* __restrict__ lo, int n)
{
    int i = blockIdx.x * blockDim.x + threadIdx.x;
    if (i >= n) return;
    float x = src[i];
    __nv_bfloat16 h = __float2bfloat16_rn(x);
    hi[i] = h;
    lo[i] = __float2bfloat16_rn(x - __bfloat162float(h));
}

__global__ __launch_bounds__(256) void detect_tok_kernel(const int* __restrict__ cap32)
{
    __shared__ int bad;
    if (threadIdx.x == 0) bad = 0;
    __syncthreads();
    for (int i = 2 * threadIdx.x + 1; i < B_ * T_; i += 2 * blockDim.x)
        if (cap32[i] != 0) bad = 1;
    __syncthreads();
    if (threadIdx.x == 0) g_tok64 = bad ? 0 : 1;
}

__global__ __launch_bounds__(256) void zero_last_kernel(float* __restrict__ out)
{
    int idx = blockIdx.x * blockDim.x + threadIdx.x;
    if (idx >= B_ * V_) return;
    int b = idx / V_, v = idx % V_;
    out[(size_t)b * T_ * V_ + (size_t)(T_ - 1) * V_ + v] = 0.f;
}

__global__ __launch_bounds__(256) void mean_enc_kernel(const float* __restrict__ enc)
{
    int b = blockIdx.y;
    int e = blockIdx.x * 256 + threadIdx.x;
    float s = 0.f;
    const float* base = enc + (size_t)b * P_ * ENC_ + e;
    for (int p = 0; p < P_; ++p) s += base[(size_t)p * ENC_];
    g_mean[b * ENC_ + e] = s * (1.f / (float)P_);
}

__global__ __launch_bounds__(256)
void build_wcat_split_kernel(const float* __restrict__ W_ih, const float* __restrict__ W_hh,
                             const float* __restrict__ b_ih, const float* __restrict__ b_hh)
{
    int idx = blockIdx.x * blockDim.x + threadIdx.x;
    if (idx < GH_) g_bcat[idx] = b_ih[idx] + b_hh[idx];
    if (idx >= GH_ * KCAT) return;
    int n = idx / KCAT, j = idx % KCAT;
    float w = (j < E_ + ENC_) ? W_ih[(size_t)n * (E_ + ENC_) + j]
                              : W_hh[(size_t)n * H_ + (j - E_ - ENC_)];
    __nv_bfloat16 h = __float2bfloat16_rn(w);
    g_Wcat_hi[idx] = h;
    g_Wcat_lo[idx] = __float2bfloat16_rn(w - __bfloat162float(h));
}

__global__ __launch_bounds__(256)
void init_h0c0_kernel(const float* __restrict__ bch, const float* __restrict__ bcc)
{
    int idx = blockIdx.x * blockDim.x + threadIdx.x;
    if (idx >= B_ * H_) return;
    int n = idx % H_;
    g_h[idx] = bch[n];
    g_c[idx] = bcc[n];
}

__global__ __launch_bounds__(256) void sh0_kernel()
{
    int idx = blockIdx.x * blockDim.x + threadIdx.x;
    if (idx < B_ * H_) g_sh[idx] = sigf(g_h[idx]);
}

// LSTM pointwise: sum gates partials + bcat, update c,h, record h
__global__ __launch_bounds__(256) void lstm_kernel(int t)
{
    int idx = blockIdx.x * blockDim.x + threadIdx.x;
    if (idx >= B_ * H_) return;
    int b = idx / H_, j = idx % H_;

    float gv[4];
#pragma unroll
    for (int q = 0; q < 4; ++q) {
        int col = q * H_ + j;
        float s = g_bcat[col];
#pragma unroll
        for (int z = 0; z < KSPLIT_GATES; ++z)
            s += g_gates_part[((size_t)z * B_ + b) * GH_ + col];
        gv[q] = s;
    }
    float i_ = sigf(gv[0]);
    float f_ = sigf(gv[1]);
    float gg = tanhf(gv[2]);
    float o_ = sigf(gv[3]);
    float c = f_ * g_c[idx] + i_ * gg;
    float h = o_ * tanhf(c);
    g_c[idx] = c;
    g_h[idx] = h;
    g_sh[idx] = sigf(h);
    g_hall[(size_t)t * B_ * H_ + idx] = h;
}

// ---------------- host orchestration ----------------
static inline float* symf(const void* s)
{
    void* p = nullptr;
    cudaGetSymbolAddress(&p, s);
    return (float*)p;
}
static inline __nv_bfloat16* symb(const void* s)
{
    void* p = nullptr;
    cudaGetSymbolAddress(&p, s);
    return (__nv_bfloat16*)p;
}

extern "C" void kernel_launch(void* const* d_in, const int* in_sizes, int n_in,
                              void* d_out, int out_size)
{
    const float* encode_out = (const float*)d_in[0];
    const void*  captions   = d_in[1];
    const float* emb        = (const float*)d_in[2];
    const float* W_ih       = (const float*)d_in[3];
    const float* b_ih       = (const float*)d_in[4];
    const float* W_hh       = (const float*)d_in[5];
    const float* b_hh       = (const float*)d_in[6];
    const float* We         = (const float*)d_in[7];
    const float* be         = (const float*)d_in[8];
    const float* Wh         = (const float*)d_in[9];
    const float* bh         = (const float*)d_in[10];
    const float* Wa         = (const float*)d_in[11];
    const float* ba         = (const float*)d_in[12];
    const float* Wch        = (const float*)d_in[13];
    const float* bch        = (const float*)d_in[14];
    const float* Wcc        = (const float*)d_in[15];
    const float* bcc        = (const float*)d_in[16];
    const float* Wfc        = (const float*)d_in[17];
    const float* bfc        = (const float*)d_in[18];
    const float* Wg         = (const float*)d_in[19];
    const float* bg         = (const float*)d_in[20];
    float* out = (float*)d_out;

    float* p_att_enc    = symf(g_att_enc);
    float* p_sh         = symf(g_sh);
    float* p_h          = symf(g_h);
    float* p_c          = symf(g_c);
    float* p_mean       = symf(g_mean);
    float* p_hall       = symf(g_hall);
    float* p_gate_part  = symf(g_gate_part);
    float* p_gates_part = symf(g_gates_part);

    __nv_bfloat16* p_enc_hi  = symb(g_enc_hi);
    __nv_bfloat16* p_enc_lo  = symb(g_enc_lo);
    __nv_bfloat16* p_We_hi   = symb(g_We_hi);
    __nv_bfloat16* p_We_lo   = symb(g_We_lo);
    __nv_bfloat16* p_Wfc_hi  = symb(g_Wfc_hi);
    __nv_bfloat16* p_Wfc_lo  = symb(g_Wfc_lo);
    __nv_bfloat16* p_Wcat_hi = symb(g_Wcat_hi);
    __nv_bfloat16* p_Wcat_lo = symb(g_Wcat_lo);
    __nv_bfloat16* p_inp_hi  = symb(g_inp_hi);
    __nv_bfloat16* p_inp_lo  = symb(g_inp_lo);
    __nv_bfloat16* p_hall_hi = symb(g_hall_hi);
    __nv_bfloat16* p_hall_lo = symb(g_hall_lo);

    // ---- prologue ----
    detect_tok_kernel<<<1, 256>>>((const int*)captions);
    zero_last_kernel<<<(B_ * V_ + 255) / 256, 256>>>(out);
    mean_enc_kernel<<<dim3(ENC_ / 256, B_), 256>>>(encode_out);

    split_kernel<<<(B_ * P_ * ENC_ + 255) / 256, 256>>>(encode_out, p_enc_hi, p_enc_lo, B_ * P_ * ENC_);
    split_kernel<<<(A_ * ENC_ + 255) / 256, 256>>>(We, p_We_hi, p_We_lo, A_ * ENC_);
    split_kernel<<<(V_ * H_ + 255) / 256, 256>>>(Wfc, p_Wfc_hi, p_Wfc_lo, V_ * H_);
    build_wcat_split_kernel<<<(GH_ * KCAT + 255) / 256, 256>>>(W_ih, W_hh, b_ih, b_hh);

    init_h0c0_kernel<<<(B_ * H_ + 255) / 256, 256>>>(bch, bcc);
    sgemm_kernel<<<dim3(H_ / BN, 1, 8), 256>>>(p_mean, Wch, p_h, nullptr,
                                               B_, H_, ENC_, H_, ENC_ / 8, 1);
    sgemm_kernel<<<dim3(H_ / BN, 1, 8), 256>>>(p_mean, Wcc, p_c, nullptr,
                                               B_, H_, ENC_, H_, ENC_ / 8, 1);
    sh0_kernel<<<(B_ * H_ + 255) / 256, 256>>>();

    // att_enc = encode_out @ We^T + be
    mma_gemm_kernel<<<dim3(A_ / 64, (B_ * P_) / 64, 1), 256>>>(
        p_enc_hi, p_enc_lo, p_We_hi, p_We_lo, p_att_enc, be,
        B_ * P_, A_, ENC_, A_, ENC_, 0);

    // ---- timesteps: 5 launches each ----
    for (int t = 0; t < T_ - 1; ++t) {
        // gate partials: sigmoid(h) @ Wg^T (split-K 4, partial buffers)
        sgemm_kernel<<<dim3(ENC_ / BN, 1, KSPLIT_GATE), 256>>>(
            p_sh, Wg, p_gate_part, nullptr, B_, ENC_, H_, ENC_, H_ / KSPLIT_GATE, 2);
        // att_h + scores + softmax
        attn_scores_kernel<<<B_, 256>>>(Wh, bh, Wa, ba);
        // weighted + gate reduce + inp build/split
        build_inp_fused_kernel<<<dim3(KCAT / 256, B_), 256>>>(encode_out, captions, emb, bg, t);
        // gates partials: inp @ Wcat^T (split-K 8, partial buffers)
        mma_gemm_kernel<<<dim3(GH_ / 64, 1, KSPLIT_GATES), 256>>>(
            p_inp_hi, p_inp_lo, p_Wcat_hi, p_Wcat_lo, p_gates_part, nullptr,
            B_, GH_, KCAT, GH_, KCAT / KSPLIT_GATES, 3);
        // lstm: reduce partials + bcat, update state
        lstm_kernel<<<(B_ * H_ + 255) / 256, 256>>>(t);
    }

    // ---- batched pred: out[b,t,:] = h_all[t,b,:] @ Wfc^T + bfc ----
    split_kernel<<<(MPRED * H_ + 255) / 256, 256>>>(p_hall, p_hall_hi, p_hall_lo, MPRED * H_);
    mma_gemm_kernel<<<dim3(MPRED / 64, (V_ + 63) / 64, 1), 256>>>(
        p_hall_hi, p_hall_lo, p_Wfc_hi, p_Wfc_lo, out, bfc,
        MPRED, V_, H_, 0 /*ldc unused*/, H_, 2);
}

// round 14
// speedup vs baseline: 1.3814x; 1.3814x over previous
#include <cuda_runtime.h>
#include <cuda_bf16.h>
#include <math.h>
#include <stdint.h>

// Problem constants
#define B_   64
#define P_   196
#define ENC_ 2048
#define H_   512
#define E_   512
#define A_   512
#define V_   30000
#define T_   20
#define GH_  2048   // 4*H
#define KCAT 3072   // E + ENC + H
#define MPRED (19 * B_)

// ---------------- scratch (static device memory; allocation-free) ----------------
__device__ __align__(16) float g_att_enc[B_ * P_ * A_];
__device__ __align__(16) float g_att_h [B_ * A_];
__device__ __align__(16) float g_scores[B_ * P_];
__device__ __align__(16) float g_alpha [B_ * P_];
__device__ __align__(16) float g_weighted[B_ * ENC_];
__device__ __align__(16) float g_sh   [B_ * H_];
__device__ __align__(16) float g_gate [B_ * ENC_];
__device__ __align__(16) float g_gates[B_ * GH_];
__device__ __align__(16) float g_h    [B_ * H_];
__device__ __align__(16) float g_c    [B_ * H_];
__device__ __align__(16) float g_mean [B_ * ENC_];
__device__ __align__(16) float g_bcat [GH_];
__device__ __align__(16) float g_hall [MPRED * H_];
__device__ int g_tok64;

// bf16 split operands (hi + lo error-compensated)
__device__ __align__(16) __nv_bfloat16 g_enc_hi [B_ * P_ * ENC_];
__device__ __align__(16) __nv_bfloat16 g_enc_lo [B_ * P_ * ENC_];
__device__ __align__(16) __nv_bfloat16 g_We_hi  [A_ * ENC_];
__device__ __align__(16) __nv_bfloat16 g_We_lo  [A_ * ENC_];
__device__ __align__(16) __nv_bfloat16 g_Wfc_hi [V_ * H_];
__device__ __align__(16) __nv_bfloat16 g_Wfc_lo [V_ * H_];
__device__ __align__(16) __nv_bfloat16 g_Wcat_hi[GH_ * KCAT];
__device__ __align__(16) __nv_bfloat16 g_Wcat_lo[GH_ * KCAT];
__device__ __align__(16) __nv_bfloat16 g_inp_hi [B_ * KCAT];
__device__ __align__(16) __nv_bfloat16 g_inp_lo [B_ * KCAT];
__device__ __align__(16) __nv_bfloat16 g_hall_hi[MPRED * H_];
__device__ __align__(16) __nv_bfloat16 g_hall_lo[MPRED * H_];

__device__ __forceinline__ float sigf(float x) { return 1.f / (1.f + __expf(-x)); }

__device__ __forceinline__ void ldsm4(uint32_t* r, uint32_t addr)
{
    asm volatile("ldmatrix.sync.aligned.m8n8.x4.shared.b16 {%0,%1,%2,%3}, [%4];"
                 : "=r"(r[0]), "=r"(r[1]), "=r"(r[2]), "=r"(r[3]) : "r"(addr));
}

__device__ __forceinline__ void mma16816(float* c, const uint32_t* a, uint32_t b0, uint32_t b1)
{
    asm volatile("mma.sync.aligned.m16n8k16.row.col.f32.bf16.bf16.f32 "
                 "{%0,%1,%2,%3}, {%4,%5,%6,%7}, {%8,%9}, {%0,%1,%2,%3};"
                 : "+f"(c[0]), "+f"(c[1]), "+f"(c[2]), "+f"(c[3])
                 : "r"(a[0]), "r"(a[1]), "r"(a[2]), "r"(a[3]), "r"(b0), "r"(b1));
}

// ========== 64x64-tile bf16-split mma GEMM (used for per-step gates) ==========
// mode 1: atomicAdd (split-K via z; bias pre-initialized in C)
#define LDSM_ 40

__global__ __launch_bounds__(256)
void mma_gemm_kernel(const __nv_bfloat16* __restrict__ Ahi, const __nv_bfloat16* __restrict__ Alo,
                     const __nv_bfloat16* __restrict__ Bhi, const __nv_bfloat16* __restrict__ Blo,
                     float* __restrict__ C, const float* __restrict__ bias,
                     int M, int N, int K, int ldc, int kchunk, int mode)
{
    __shared__ __nv_bfloat16 sAh[64 * LDSM_], sAl[64 * LDSM_];
    __shared__ __nv_bfloat16 sBh[64 * LDSM_], sBl[64 * LDSM_];

    const int tid  = threadIdx.x;
    const int lane = tid & 31;
    const int warp = tid >> 5;
    const int wm = (warp & 1) * 32;
    const int wn = (warp >> 1) * 16;

    const int n0 = blockIdx.x * 64;
    const int m0 = blockIdx.y * 64;
    const int kbeg = blockIdx.z * kchunk;
    const int kend = kbeg + kchunk;

    float acc[2][2][4];
#pragma unroll
    for (int i = 0; i < 2; ++i)
#pragma unroll
        for (int j = 0; j < 2; ++j)
#pragma unroll
            for (int q = 0; q < 4; ++q) acc[i][j][q] = 0.f;

    const int lrow   = tid >> 2;
    const int lchunk = (tid & 3) << 3;

    const uint32_t sAh_b = (uint32_t)__cvta_generic_to_shared(sAh);
    const uint32_t sAl_b = (uint32_t)__cvta_generic_to_shared(sAl);
    const uint32_t sBh_b = (uint32_t)__cvta_generic_to_shared(sBh);
    const uint32_t sBl_b = (uint32_t)__cvta_generic_to_shared(sBl);

    const int fr   = lane & 15;
    const int fcof = (lane >> 4) << 3;
    const int aoff0 = (wm +  0 + fr) * LDSM_ + fcof;
    const int aoff1 = (wm + 16 + fr) * LDSM_ + fcof;
    const int boff  = (wn +       fr) * LDSM_ + fcof;

    for (int k0 = kbeg; k0 < kend; k0 += 32) {
        {
            size_t gofs = (size_t)(m0 + lrow) * K + k0 + lchunk;
            *(uint4*)&sAh[lrow * LDSM_ + lchunk] = *(const uint4*)(Ahi + gofs);
            *(uint4*)&sAl[lrow * LDSM_ + lchunk] = *(const uint4*)(Alo + gofs);
        }
        {
            uint4 vh = make_uint4(0u, 0u, 0u, 0u), vl = vh;
            int n = n0 + lrow;
            if (n < N) {
                size_t gofs = (size_t)n * K + k0 + lchunk;
                vh = *(const uint4*)(Bhi + gofs);
                vl = *(const uint4*)(Blo + gofs);
            }
            *(uint4*)&sBh[lrow * LDSM_ + lchunk] = vh;
            *(uint4*)&sBl[lrow * LDSM_ + lchunk] = vl;
        }
        __syncthreads();

#pragma unroll
        for (int kk = 0; kk < 32; kk += 16) {
            uint32_t ah0[4], ah1[4], al0[4], al1[4], bh[4], bl[4];
            ldsm4(ah0, sAh_b + (uint32_t)(aoff0 + kk) * 2);
            ldsm4(ah1, sAh_b + (uint32_t)(aoff1 + kk) * 2);
            ldsm4(al0, sAl_b + (uint32_t)(aoff0 + kk) * 2);
            ldsm4(al1, sAl_b + (uint32_t)(aoff1 + kk) * 2);
            ldsm4(bh,  sBh_b + (uint32_t)(boff  + kk) * 2);
            ldsm4(bl,  sBl_b + (uint32_t)(boff  + kk) * 2);
            mma16816(acc[0][0], ah0, bh[0], bh[2]);
            mma16816(acc[0][1], ah0, bh[1], bh[3]);
            mma16816(acc[1][0], ah1, bh[0], bh[2]);
            mma16816(acc[1][1], ah1, bh[1], bh[3]);
            mma16816(acc[0][0], ah0, bl[0], bl[2]);
            mma16816(acc[0][1], ah0, bl[1], bl[3]);
            mma16816(acc[1][0], ah1, bl[0], bl[2]);
            mma16816(acc[1][1], ah1, bl[1], bl[3]);
            mma16816(acc[0][0], al0, bh[0], bh[2]);
            mma16816(acc[0][1], al0, bh[1], bh[3]);
            mma16816(acc[1][0], al1, bh[0], bh[2]);
            mma16816(acc[1][1], al1, bh[1], bh[3]);
        }
        __syncthreads();
    }

#pragma unroll
    for (int mt = 0; mt < 2; ++mt) {
#pragma unroll
        for (int nt = 0; nt < 2; ++nt) {
            int row = m0 + wm + mt * 16 + (lane >> 2);
            int col = n0 + wn + nt * 8 + ((lane & 3) << 1);
            const float* a = acc[mt][nt];
#pragma unroll
            for (int hh = 0; hh < 2; ++hh) {
                int rr = row + hh * 8;
                float v0 = a[hh * 2 + 0], v1 = a[hh * 2 + 1];
                if (mode == 1) {
                    if (col < N)     atomicAdd(&C[(size_t)rr * ldc + col],     v0);
                    if (col + 1 < N) atomicAdd(&C[(size_t)rr * ldc + col + 1], v1);
                } else {
                    if (col < N)     C[(size_t)rr * ldc + col]     = v0 + (bias ? bias[col]     : 0.f);
                    if (col + 1 < N) C[(size_t)rr * ldc + col + 1] = v1 + (bias ? bias[col + 1] : 0.f);
                }
            }
        }
    }
}

// ========== 128x128-tile bf16-split mma GEMM (att_enc + batched pred) =========
// mode 0: C[m*ldc+n] = acc + bias[n]   grid: x=N-tiles, y=M-tiles
// mode 2: pred scatter row m=(t*64+b) -> C[b*T*V + t*V + n] = acc + bias[n]
//         grid: x=M-tiles, y=N-tiles  (consecutive x share the B tile in L2)
#define LDA_ 40

__global__ __launch_bounds__(256)
void mma_gemm128_kernel(const __nv_bfloat16* __restrict__ Ahi, const __nv_bfloat16* __restrict__ Alo,
                        const __nv_bfloat16* __restrict__ Bhi, const __nv_bfloat16* __restrict__ Blo,
                        float* __restrict__ C, const float* __restrict__ bias,
                        int M, int N, int K, int ldc, int mode)
{
    __shared__ __nv_bfloat16 sAh[128 * LDA_], sAl[128 * LDA_];
    __shared__ __nv_bfloat16 sBh[128 * LDA_], sBl[128 * LDA_];

    const int tid  = threadIdx.x;
    const int lane = tid & 31;
    const int warp = tid >> 5;
    const int wm = (warp & 1) * 64;    // warp m offset (2 chunks of 64)
    const int wn = (warp >> 1) * 32;   // warp n offset (4 chunks of 32)

    int m0, n0;
    if (mode == 2) { m0 = blockIdx.x * 128; n0 = blockIdx.y * 128; }
    else           { n0 = blockIdx.x * 128; m0 = blockIdx.y * 128; }

    float acc[4][4][4];
#pragma unroll
    for (int i = 0; i < 4; ++i)
#pragma unroll
        for (int j = 0; j < 4; ++j)
#pragma unroll
            for (int q = 0; q < 4; ++q) acc[i][j][q] = 0.f;

    // loader: 256 threads, two passes cover 128 rows x 32 cols per array
    const int r1 = tid >> 2;            // 0..63
    const int c1 = (tid & 3) << 3;      // 0,8,16,24

    const uint32_t sAh_b = (uint32_t)__cvta_generic_to_shared(sAh);
    const uint32_t sAl_b = (uint32_t)__cvta_generic_to_shared(sAl);
    const uint32_t sBh_b = (uint32_t)__cvta_generic_to_shared(sBh);
    const uint32_t sBl_b = (uint32_t)__cvta_generic_to_shared(sBl);

    const int fr   = lane & 15;
    const int fcof = (lane >> 4) << 3;
    int aoff[4], boff[2];
#pragma unroll
    for (int i = 0; i < 4; ++i) aoff[i] = (wm + i * 16 + fr) * LDA_ + fcof;
#pragma unroll
    for (int j = 0; j < 2; ++j) boff[j] = (wn + j * 16 + fr) * LDA_ + fcof;

    for (int k0 = 0; k0 < K; k0 += 32) {
        // ---- A (rows clamped to M-1; clamped rows' results are discarded) ----
        {
            int am = m0 + r1;       if (am >= M) am = M - 1;
            size_t g = (size_t)am * K + k0 + c1;
            *(uint4*)&sAh[r1 * LDA_ + c1] = *(const uint4*)(Ahi + g);
            *(uint4*)&sAl[r1 * LDA_ + c1] = *(const uint4*)(Alo + g);
            int am2 = m0 + r1 + 64; if (am2 >= M) am2 = M - 1;
            size_t g2 = (size_t)am2 * K + k0 + c1;
            *(uint4*)&sAh[(r1 + 64) * LDA_ + c1] = *(const uint4*)(Ahi + g2);
            *(uint4*)&sAl[(r1 + 64) * LDA_ + c1] = *(const uint4*)(Alo + g2);
        }
        // ---- B (zero-fill beyond N) ----
        {
            uint4 vh = make_uint4(0u, 0u, 0u, 0u), vl = vh;
            int n = n0 + r1;
            if (n < N) {
                size_t g = (size_t)n * K + k0 + c1;
                vh = *(const uint4*)(Bhi + g);
                vl = *(const uint4*)(Blo + g);
            }
            *(uint4*)&sBh[r1 * LDA_ + c1] = vh;
            *(uint4*)&sBl[r1 * LDA_ + c1] = vl;

            uint4 vh2 = make_uint4(0u, 0u, 0u, 0u), vl2 = vh2;
            int n2 = n0 + r1 + 64;
            if (n2 < N) {
                size_t g2 = (size_t)n2 * K + k0 + c1;
                vh2 = *(const uint4*)(Bhi + g2);
                vl2 = *(const uint4*)(Blo + g2);
            }
            *(uint4*)&sBh[(r1 + 64) * LDA_ + c1] = vh2;
            *(uint4*)&sBl[(r1 + 64) * LDA_ + c1] = vl2;
        }
        __syncthreads();

#pragma unroll
        for (int kk = 0; kk < 32; kk += 16) {
            uint32_t ah[4][4], al[4][4], bh[2][4], bl[2][4];
#pragma unroll
            for (int i = 0; i < 4; ++i) {
                ldsm4(ah[i], sAh_b + (uint32_t)(aoff[i] + kk) * 2);
                ldsm4(al[i], sAl_b + (uint32_t)(aoff[i] + kk) * 2);
            }
#pragma unroll
            for (int j = 0; j < 2; ++j) {
                ldsm4(bh[j], sBh_b + (uint32_t)(boff[j] + kk) * 2);
                ldsm4(bl[j], sBl_b + (uint32_t)(boff[j] + kk) * 2);
            }
#pragma unroll
            for (int mi = 0; mi < 4; ++mi) {
#pragma unroll
                for (int nj = 0; nj < 4; ++nj) {
                    const int j = nj >> 1, s = nj & 1;
                    mma16816(acc[mi][nj], ah[mi], bh[j][s], bh[j][s + 2]);
                    mma16816(acc[mi][nj], ah[mi], bl[j][s], bl[j][s + 2]);
                    mma16816(acc[mi][nj], al[mi], bh[j][s], bh[j][s + 2]);
                }
            }
        }
        __syncthreads();
    }

    // epilogue
#pragma unroll
    for (int mi = 0; mi < 4; ++mi) {
#pragma unroll
        for (int nj = 0; nj < 4; ++nj) {
            int row = m0 + wm + mi * 16 + (lane >> 2);
            int col = n0 + wn + nj * 8 + ((lane & 3) << 1);
            const float* a = acc[mi][nj];
#pragma unroll
            for (int hh = 0; hh < 2; ++hh) {
                int rr = row + hh * 8;
                if (rr >= M) continue;
                float v0 = a[hh * 2 + 0], v1 = a[hh * 2 + 1];
                if (mode == 0) {
                    if (col < N)     C[(size_t)rr * ldc + col]     = v0 + (bias ? bias[col]     : 0.f);
                    if (col + 1 < N) C[(size_t)rr * ldc + col + 1] = v1 + (bias ? bias[col + 1] : 0.f);
                } else {
                    int tt = rr >> 6, bb = rr & 63;
                    size_t o = (size_t)bb * T_ * V_ + (size_t)tt * V_;
                    if (col < N)     C[o + col]     = v0 + bias[col];
                    if (col + 1 < N) C[o + col + 1] = v1 + bias[col + 1];
                }
            }
        }
    }
}

// ---------------- fp32 SIMT SGEMM (small GEMMs only) ----------------
#define BM 64
#define BN 64
#define BK 16

__global__ __launch_bounds__(256)
void sgemm_kernel(const float* __restrict__ Amat, const float* __restrict__ Bmat,
                  float* __restrict__ C, const float* __restrict__ bias,
                  int M, int N, int K, int ldc, int kchunk, int mode)
{
    __shared__ float As[BK][BM + 4];
    __shared__ float Bs[BK][BN + 4];

    const int tid = threadIdx.x;
    const int tx = tid & 15;
    const int ty = tid >> 4;
    const int m0 = blockIdx.y * BM;
    const int n0 = blockIdx.x * BN;
    const int kbeg = blockIdx.z * kchunk;
    const int kend = kbeg + kchunk;
    const int lr = tid >> 2;
    const int lc = (tid & 3) << 2;

    float acc[4][4] = {};

    for (int k0 = kbeg; k0 < kend; k0 += BK) {
        float4 a4 = make_float4(0.f, 0.f, 0.f, 0.f);
        int am = m0 + lr;
        if (am < M) a4 = *(const float4*)(Amat + (size_t)am * K + k0 + lc);
        As[lc + 0][lr] = a4.x; As[lc + 1][lr] = a4.y;
        As[lc + 2][lr] = a4.z; As[lc + 3][lr] = a4.w;

        float4 b4 = make_float4(0.f, 0.f, 0.f, 0.f);
        int bn = n0 + lr;
        if (bn < N) b4 = *(const float4*)(Bmat + (size_t)bn * K + k0 + lc);
        Bs[lc + 0][lr] = b4.x; Bs[lc + 1][lr] = b4.y;
        Bs[lc + 2][lr] = b4.z; Bs[lc + 3][lr] = b4.w;

        __syncthreads();
#pragma unroll
        for (int k = 0; k < BK; ++k) {
            float4 ra = *(const float4*)&As[k][ty << 2];
            float4 rb = *(const float4*)&Bs[k][tx << 2];
            acc[0][0] += ra.x * rb.x; acc[0][1] += ra.x * rb.y;
            acc[0][2] += ra.x * rb.z; acc[0][3] += ra.x * rb.w;
            acc[1][0] += ra.y * rb.x; acc[1][1] += ra.y * rb.y;
            acc[1][2] += ra.y * rb.z; acc[1][3] += ra.y * rb.w;
            acc[2][0] += ra.z * rb.x; acc[2][1] += ra.z * rb.y;
            acc[2][2] += ra.z * rb.z; acc[2][3] += ra.z * rb.w;
            acc[3][0] += ra.w * rb.x; acc[3][1] += ra.w * rb.y;
            acc[3][2] += ra.w * rb.z; acc[3][3] += ra.w * rb.w;
        }
        __syncthreads();
    }

#pragma unroll
    for (int i = 0; i < 4; ++i) {
        int m = m0 + (ty << 2) + i;
        if (m >= M) continue;
#pragma unroll
        for (int j = 0; j < 4; ++j) {
            int n = n0 + (tx << 2) + j;
            if (n >= N) continue;
            if (mode == 0) C[(size_t)m * ldc + n] = acc[i][j] + (bias ? bias[n] : 0.f);
            else           atomicAdd(&C[(size_t)m * ldc + n], acc[i][j]);
        }
    }
}

// ---------------- small custom kernels ----------------

// vectorized bf16 hi/lo split (n must be a multiple of 4; all call sites are)
__global__ __launch_bounds__(256)
void split4_kernel(const float4* __restrict__ src, uint2* __restrict__ hi,
                   uint2* __restrict__ lo, int n4)
{
    int i = blockIdx.x * blockDim.x + threadIdx.x;
    if (i >= n4) return;
    float4 x = src[i];
    __nv_bfloat16 h0 = __float2bfloat16_rn(x.x);
    __nv_bfloat16 h1 = __float2bfloat16_rn(x.y);
    __nv_bfloat16 h2 = __float2bfloat16_rn(x.z);
    __nv_bfloat16 h3 = __float2bfloat16_rn(x.w);
    __nv_bfloat16 l0 = __float2bfloat16_rn(x.x - __bfloat162float(h0));
    __nv_bfloat16 l1 = __float2bfloat16_rn(x.y - __bfloat162float(h1));
    __nv_bfloat16 l2 = __float2bfloat16_rn(x.z - __bfloat162float(h2));
    __nv_bfloat16 l3 = __float2bfloat16_rn(x.w - __bfloat162float(h3));
    __nv_bfloat162 hp0 = __halves2bfloat162(h0, h1);
    __nv_bfloat162 hp1 = __halves2bfloat162(h2, h3);
    __nv_bfloat162 lp0 = __halves2bfloat162(l0, l1);
    __nv_bfloat162 lp1 = __halves2bfloat162(l2, l3);
    uint2 hv, lv;
    hv.x = *reinterpret_cast<unsigned*>(&hp0);
    hv.y = *reinterpret_cast<unsigned*>(&hp1);
    lv.x = *reinterpret_cast<unsigned*>(&lp0);
    lv.y = *reinterpret_cast<unsigned*>(&lp1);
    hi[i] = hv;
    lo[i] = lv;
}

__global__ __launch_bounds__(256) void detect_tok_kernel(const int* __restrict__ cap32)
{
    __shared__ int bad;
    if (threadIdx.x == 0) bad = 0;
    __syncthreads();
    for (int i = 2 * threadIdx.x + 1; i < B_ * T_; i += 2 * blockDim.x)
        if (cap32[i] != 0) bad = 1;
    __syncthreads();
    if (threadIdx.x == 0) g_tok64 = bad ? 0 : 1;
}

__global__ __launch_bounds__(256) void zero_last_kernel(float* __restrict__ out)
{
    int idx = blockIdx.x * blockDim.x + threadIdx.x;
    if (idx >= B_ * V_) return;
    int b = idx / V_, v = idx % V_;
    out[(size_t)b * T_ * V_ + (size_t)(T_ - 1) * V_ + v] = 0.f;
}

__global__ __launch_bounds__(256) void mean_enc_kernel(const float* __restrict__ enc)
{
    int b = blockIdx.y;
    int e = blockIdx.x * 256 + threadIdx.x;
    float s = 0.f;
    const float* base = enc + (size_t)b * P_ * ENC_ + e;
    for (int p = 0; p < P_; ++p) s += base[(size_t)p * ENC_];
    g_mean[b * ENC_ + e] = s * (1.f / (float)P_);
}

__global__ __launch_bounds__(256)
void build_wcat_split_kernel(const float* __restrict__ W_ih, const float* __restrict__ W_hh,
                             const float* __restrict__ b_ih, const float* __restrict__ b_hh)
{
    int idx = blockIdx.x * blockDim.x + threadIdx.x;
    if (idx < GH_) g_bcat[idx] = b_ih[idx] + b_hh[idx];
    if (idx >= GH_ * KCAT) return;
    int n = idx / KCAT, j = idx % KCAT;
    float w = (j < E_ + ENC_) ? W_ih[(size_t)n * (E_ + ENC_) + j]
                              : W_hh[(size_t)n * H_ + (j - E_ - ENC_)];
    __nv_bfloat16 h = __float2bfloat16_rn(w);
    g_Wcat_hi[idx] = h;
    g_Wcat_lo[idx] = __float2bfloat16_rn(w - __bfloat162float(h));
}

__global__ __launch_bounds__(256)
void init_h0c0_kernel(const float* __restrict__ bch, const float* __restrict__ bcc)
{
    int idx = blockIdx.x * blockDim.x + threadIdx.x;
    if (idx >= B_ * H_) return;
    int n = idx % H_;
    g_h[idx] = bch[n];
    g_c[idx] = bcc[n];
}

__global__ __launch_bounds__(256) void sh0_kernel()
{
    int idx = blockIdx.x * blockDim.x + threadIdx.x;
    if (idx < B_ * H_) g_sh[idx] = sigf(g_h[idx]);
}

__global__ __launch_bounds__(256)
void init3_kernel(const float* __restrict__ bh, const float* __restrict__ bg)
{
    int idx = blockIdx.x * blockDim.x + threadIdx.x;
    if (idx < B_ * A_) g_att_h[idx] = bh[idx % A_];
    int i2 = idx - B_ * A_;
    if (i2 >= 0 && i2 < B_ * ENC_) g_gate[i2] = bg[i2 % ENC_];
    int i3 = idx - B_ * A_ - B_ * ENC_;
    if (i3 >= 0 && i3 < B_ * GH_) g_gates[i3] = g_bcat[i3 % GH_];
}

__global__ __launch_bounds__(256)
void scores_kernel(const float* __restrict__ Wa, const float* __restrict__ ba)
{
    __shared__ float s_h[A_];
    __shared__ float s_w[A_];
    int b = blockIdx.y;
    for (int i = threadIdx.x; i < A_; i += 256) {
        s_h[i] = g_att_h[b * A_ + i];
        s_w[i] = Wa[i];
    }
    __syncthreads();
    int w = threadIdx.x >> 5, lane = threadIdx.x & 31;
    int p = blockIdx.x * 8 + w;
    if (p >= P_) return;
    const float* row = g_att_enc + ((size_t)(b * P_ + p)) * A_;
    float s = 0.f;
    for (int a = lane; a < A_; a += 32) {
        float v = row[a] + s_h[a];
        s += fmaxf(v, 0.f) * s_w[a];
    }
#pragma unroll
    for (int o = 16; o; o >>= 1) s += __shfl_xor_sync(0xffffffff, s, o);
    if (lane == 0) g_scores[b * P_ + p] = s + ba[0];
}

__global__ __launch_bounds__(256) void softmax_kernel()
{
    __shared__ float red[256];
    int b = blockIdx.x, t = threadIdx.x;
    float v = (t < P_) ? g_scores[b * P_ + t] : -1e30f;
    red[t] = v; __syncthreads();
    for (int s = 128; s; s >>= 1) { if (t < s) red[t] = fmaxf(red[t], red[t + s]); __syncthreads(); }
    float mx = red[0]; __syncthreads();
    float e = (t < P_) ? __expf(v - mx) : 0.f;
    red[t] = e; __syncthreads();
    for (int s = 128; s; s >>= 1) { if (t < s) red[t] += red[t + s]; __syncthreads(); }
    float inv = 1.f / red[0];
    if (t < P_) g_alpha[b * P_ + t] = e * inv;
}

__global__ __launch_bounds__(256) void weighted_kernel(const float* __restrict__ enc)
{
    __shared__ float sa[P_];
    int b = blockIdx.y;
    int e = blockIdx.x * 256 + threadIdx.x;
    for (int i = threadIdx.x; i < P_; i += 256) sa[i] = g_alpha[b * P_ + i];
    __syncthreads();
    const float* base = enc + (size_t)b * P_ * ENC_ + e;
    float s = 0.f;
#pragma unroll 4
    for (int p = 0; p < P_; ++p) s += sa[p] * base[(size_t)p * ENC_];
    g_weighted[b * ENC_ + e] = s;
}

__global__ __launch_bounds__(256)
void build_inp_split_kernel(const void* __restrict__ cap, const float* __restrict__ emb, int t)
{
    int idx = blockIdx.x * blockDim.x + threadIdx.x;
    if (idx >= B_ * KCAT) return;
    int b = idx / KCAT, j = idx % KCAT;
    float v;
    if (j < E_) {
        long long tok = g_tok64 ? ((const long long*)cap)[b * T_ + t]
                                : (long long)((const int*)cap)[b * T_ + t];
        v = emb[(size_t)tok * E_ + j];
    } else if (j < E_ + ENC_) {
        int e = j - E_;
        v = g_weighted[b * ENC_ + e] * g_gate[b * ENC_ + e];
    } else {
        v = g_h[b * H_ + (j - E_ - ENC_)];
    }
    __nv_bfloat16 h = __float2bfloat16_rn(v);
    g_inp_hi[idx] = h;
    g_inp_lo[idx] = __float2bfloat16_rn(v - __bfloat162float(h));
}

__global__ __launch_bounds__(256) void lstm_kernel(int t)
{
    int idx = blockIdx.x * blockDim.x + threadIdx.x;
    if (idx >= B_ * H_) return;
    int b = idx / H_, j = idx % H_;
    const float* g = g_gates + (size_t)b * GH_;
    float i_ = sigf(g[j]);
    float f_ = sigf(g[H_ + j]);
    float gg = tanhf(g[2 * H_ + j]);
    float o_ = sigf(g[3 * H_ + j]);
    float c = f_ * g_c[idx] + i_ * gg;
    float h = o_ * tanhf(c);
    g_c[idx] = c;
    g_h[idx] = h;
    g_sh[idx] = sigf(h);
    g_hall[(size_t)t * B_ * H_ + idx] = h;
}

// ---------------- host orchestration ----------------
static inline float* symf(const void* s)
{
    void* p = nullptr;
    cudaGetSymbolAddress(&p, s);
    return (float*)p;
}
static inline __nv_bfloat16* symb(const void* s)
{
    void* p = nullptr;
    cudaGetSymbolAddress(&p, s);
    return (__nv_bfloat16*)p;
}

extern "C" void kernel_launch(void* const* d_in, const int* in_sizes, int n_in,
                              void* d_out, int out_size)
{
    const float* encode_out = (const float*)d_in[0];
    const void*  captions   = d_in[1];
    const float* emb        = (const float*)d_in[2];
    const float* W_ih       = (const float*)d_in[3];
    const float* b_ih       = (const float*)d_in[4];
    const float* W_hh       = (const float*)d_in[5];
    const float* b_hh       = (const float*)d_in[6];
    const float* We         = (const float*)d_in[7];
    const float* be         = (const float*)d_in[8];
    const float* Wh         = (const float*)d_in[9];
    const float* bh         = (const float*)d_in[10];
    const float* Wa         = (const float*)d_in[11];
    const float* ba         = (const float*)d_in[12];
    const float* Wch        = (const float*)d_in[13];
    const float* bch        = (const float*)d_in[14];
    const float* Wcc        = (const float*)d_in[15];
    const float* bcc        = (const float*)d_in[16];
    const float* Wfc        = (const float*)d_in[17];
    const float* bfc        = (const float*)d_in[18];
    const float* Wg         = (const float*)d_in[19];
    const float* bg         = (const float*)d_in[20];
    float* out = (float*)d_out;

    float* p_att_enc = symf(g_att_enc);
    float* p_att_h   = symf(g_att_h);
    float* p_sh      = symf(g_sh);
    float* p_gate    = symf(g_gate);
    float* p_gates   = symf(g_gates);
    float* p_h       = symf(g_h);
    float* p_c       = symf(g_c);
    float* p_mean    = symf(g_mean);
    float* p_hall    = symf(g_hall);

    __nv_bfloat16* p_enc_hi  = symb(g_enc_hi);
    __nv_bfloat16* p_enc_lo  = symb(g_enc_lo);
    __nv_bfloat16* p_We_hi   = symb(g_We_hi);
    __nv_bfloat16* p_We_lo   = symb(g_We_lo);
    __nv_bfloat16* p_Wfc_hi  = symb(g_Wfc_hi);
    __nv_bfloat16* p_Wfc_lo  = symb(g_Wfc_lo);
    __nv_bfloat16* p_Wcat_hi = symb(g_Wcat_hi);
    __nv_bfloat16* p_Wcat_lo = symb(g_Wcat_lo);
    __nv_bfloat16* p_inp_hi  = symb(g_inp_hi);
    __nv_bfloat16* p_inp_lo  = symb(g_inp_lo);
    __nv_bfloat16* p_hall_hi = symb(g_hall_hi);
    __nv_bfloat16* p_hall_lo = symb(g_hall_lo);

    // ---- prologue ----
    detect_tok_kernel<<<1, 256>>>((const int*)captions);
    zero_last_kernel<<<(B_ * V_ + 255) / 256, 256>>>(out);
    mean_enc_kernel<<<dim3(ENC_ / 256, B_), 256>>>(encode_out);

    split4_kernel<<<(B_ * P_ * ENC_ / 4 + 255) / 256, 256>>>(
        (const float4*)encode_out, (uint2*)p_enc_hi, (uint2*)p_enc_lo, B_ * P_ * ENC_ / 4);
    split4_kernel<<<(A_ * ENC_ / 4 + 255) / 256, 256>>>(
        (const float4*)We, (uint2*)p_We_hi, (uint2*)p_We_lo, A_ * ENC_ / 4);
    split4_kernel<<<(V_ * H_ / 4 + 255) / 256, 256>>>(
        (const float4*)Wfc, (uint2*)p_Wfc_hi, (uint2*)p_Wfc_lo, V_ * H_ / 4);
    build_wcat_split_kernel<<<(GH_ * KCAT + 255) / 256, 256>>>(W_ih, W_hh, b_ih, b_hh);

    init_h0c0_kernel<<<(B_ * H_ + 255) / 256, 256>>>(bch, bcc);
    sgemm_kernel<<<dim3(H_ / BN, 1, 8), 256>>>(p_mean, Wch, p_h, nullptr,
                                               B_, H_, ENC_, H_, ENC_ / 8, 1);
    sgemm_kernel<<<dim3(H_ / BN, 1, 8), 256>>>(p_mean, Wcc, p_c, nullptr,
                                               B_, H_, ENC_, H_, ENC_ / 8, 1);
    sh0_kernel<<<(B_ * H_ + 255) / 256, 256>>>();

    // att_enc = encode_out @ We^T + be   (128x128 tensor-core GEMM)
    mma_gemm128_kernel<<<dim3(A_ / 128, (B_ * P_) / 128), 256>>>(
        p_enc_hi, p_enc_lo, p_We_hi, p_We_lo, p_att_enc, be,
        B_ * P_, A_, ENC_, A_, 0);

    const int INIT3_N = B_ * A_ + B_ * ENC_ + B_ * GH_;

    // ---- timesteps (identical to the 2697us R6 structure) ----
    for (int t = 0; t < T_ - 1; ++t) {
        init3_kernel<<<(INIT3_N + 255) / 256, 256>>>(bh, bg);
        sgemm_kernel<<<dim3(A_ / BN, 1, 8), 256>>>(p_h, Wh, p_att_h, nullptr,
                                                   B_, A_, H_, A_, H_ / 8, 1);
        scores_kernel<<<dim3((P_ + 7) / 8, B_), 256>>>(Wa, ba);
        softmax_kernel<<<B_, 256>>>();
        weighted_kernel<<<dim3(ENC_ / 256, B_), 256>>>(encode_out);
        sgemm_kernel<<<dim3(ENC_ / BN, 1, 4), 256>>>(p_sh, Wg, p_gate, nullptr,
                                                     B_, ENC_, H_, ENC_, H_ / 4, 1);
        build_inp_split_kernel<<<(B_ * KCAT + 255) / 256, 256>>>(captions, emb, t);
        mma_gemm_kernel<<<dim3(GH_ / 64, 1, 8), 256>>>(
            p_inp_hi, p_inp_lo, p_Wcat_hi, p_Wcat_lo, p_gates, nullptr,
            B_, GH_, KCAT, GH_, KCAT / 8, 1);
        lstm_kernel<<<(B_ * H_ + 255) / 256, 256>>>(t);
    }

    // ---- batched pred: out[b,t,:] = h_all[t,b,:] @ Wfc^T + bfc (128x128) ----
    split4_kernel<<<(MPRED * H_ / 4 + 255) / 256, 256>>>(
        (const float4*)p_hall, (uint2*)p_hall_hi, (uint2*)p_hall_lo, MPRED * H_ / 4);
    mma_gemm128_kernel<<<dim3((MPRED + 127) / 128, (V_ + 127) / 128), 256>>>(
        p_hall_hi, p_hall_lo, p_Wfc_hi, p_Wfc_lo, out, bfc,
        MPRED, V_, H_, 0 /*ldc unused*/, 2);
}